// round 1
// baseline (speedup 1.0000x reference)
#include <cuda_runtime.h>
#include <math.h>

// Problem constants (fixed by setup_inputs)
#define LL 2
#define NN1 8
#define NN2 8
#define PP 1024
#define DD 768
#define PH 32
#define PW 32
#define IMG 512

// Scratch (device globals; no allocation allowed)
__device__ float g_fa[LL * NN1 * PP * DD];      // normalized feats
__device__ float g_fb[LL * NN2 * PP * DD];      // normalized nfeats
__device__ float g_maxdot[LL * NN1 * NN2 * PP]; // max_p2 cos-sim
__device__ float g_sp[LL * NN1 * NN2 * PP];     // sp values
__device__ float g_maxp[LL * NN1 * NN2];        // max_p sp per (l,n1,n2)
__device__ float g_spbar[NN1 * PP];             // mean over (l,n2) of sp

// ---------------------------------------------------------------------------
// Kernel 1: L2-normalize rows of [rows, 768]. One warp per row, float4 loads.
// which==0 -> write g_fa, which==1 -> write g_fb
// ---------------------------------------------------------------------------
__global__ __launch_bounds__(256) void normalize_kernel(const float* __restrict__ in,
                                                        int which, int nrows) {
    int row  = blockIdx.x * 8 + (threadIdx.x >> 5);
    int lane = threadIdx.x & 31;
    if (row >= nrows) return;
    float* outbase = which ? g_fb : g_fa;
    const float4* src = (const float4*)(in + (size_t)row * DD);
    float4* dst = (float4*)(outbase + (size_t)row * DD);

    float4 v[6];
    float ss = 0.f;
#pragma unroll
    for (int i = 0; i < 6; i++) {
        v[i] = src[lane + 32 * i];
        ss += v[i].x * v[i].x + v[i].y * v[i].y + v[i].z * v[i].z + v[i].w * v[i].w;
    }
#pragma unroll
    for (int o = 16; o > 0; o >>= 1) ss += __shfl_xor_sync(0xffffffffu, ss, o);
    float inv = 1.0f / sqrtf(ss);
#pragma unroll
    for (int i = 0; i < 6; i++) {
        v[i].x *= inv; v[i].y *= inv; v[i].z *= inv; v[i].w *= inv;
        dst[lane + 32 * i] = v[i];
    }
}

// ---------------------------------------------------------------------------
// Kernel 2: fused GEMM + row-max.
// For pair = (l,n1,n2): S = A[1024,768] * B[1024,768]^T, keep max over columns.
// Block = 128-row strip of A, loops over all 8 column tiles (128 cols each).
// 256 threads, 8x8 register tile, BK=16 shared staging.
// ---------------------------------------------------------------------------
#define BM 128
#define BN 128
#define BK 16
#define TM 8
#define TN 8

__global__ __launch_bounds__(256) void distmax_kernel() {
    const int pair = blockIdx.y;          // 0..127 = ((l*8 + n1)*8 + n2)
    const int l  = pair >> 6;
    const int n1 = (pair >> 3) & 7;
    const int n2 = pair & 7;
    const float* __restrict__ A = g_fa + (((size_t)l * NN1 + n1) * PP) * DD;
    const float* __restrict__ B = g_fb + (((size_t)l * NN2 + n2) * PP) * DD;
    const int row0 = blockIdx.x * BM;

    __shared__ float As[BK][BM];
    __shared__ float Bs[BK][BN];

    const int tid = threadIdx.x;
    const int tx = tid & 15;   // col group
    const int ty = tid >> 4;   // row group

    float rmax[TM];
#pragma unroll
    for (int i = 0; i < TM; i++) rmax[i] = -2.0f;

    for (int ct = 0; ct < PP / BN; ct++) {
        const int col0 = ct * BN;
        float acc[TM][TN];
#pragma unroll
        for (int i = 0; i < TM; i++)
#pragma unroll
            for (int j = 0; j < TN; j++) acc[i][j] = 0.f;

        for (int k0 = 0; k0 < DD; k0 += BK) {
            // Load 128x16 tiles of A and B into shared (transposed to [k][m]).
            // 512 float4 per tile, 256 threads -> 2 float4 each per tile.
#pragma unroll
            for (int jj = 0; jj < 2; jj++) {
                int idx = tid + 256 * jj;
                int r  = idx >> 2;
                int c4 = (idx & 3) * 4;
                float4 a4 = *(const float4*)(A + (size_t)(row0 + r) * DD + k0 + c4);
                As[c4 + 0][r] = a4.x; As[c4 + 1][r] = a4.y;
                As[c4 + 2][r] = a4.z; As[c4 + 3][r] = a4.w;
                float4 b4 = *(const float4*)(B + (size_t)(col0 + r) * DD + k0 + c4);
                Bs[c4 + 0][r] = b4.x; Bs[c4 + 1][r] = b4.y;
                Bs[c4 + 2][r] = b4.z; Bs[c4 + 3][r] = b4.w;
            }
            __syncthreads();
#pragma unroll
            for (int kk = 0; kk < BK; kk++) {
                float ar[TM], br[TN];
#pragma unroll
                for (int i = 0; i < TM; i++) ar[i] = As[kk][ty * TM + i];
#pragma unroll
                for (int j = 0; j < TN; j++) br[j] = Bs[kk][tx * TN + j];
#pragma unroll
                for (int i = 0; i < TM; i++)
#pragma unroll
                    for (int j = 0; j < TN; j++) acc[i][j] += ar[i] * br[j];
            }
            __syncthreads();
        }
        // fold this column tile into running row max
#pragma unroll
        for (int i = 0; i < TM; i++) {
            float m = acc[i][0];
#pragma unroll
            for (int j = 1; j < TN; j++) m = fmaxf(m, acc[i][j]);
            rmax[i] = fmaxf(rmax[i], m);
        }
    }

    // reduce across the 16 tx lanes sharing the same rows (within half-warp)
#pragma unroll
    for (int o = 8; o > 0; o >>= 1) {
#pragma unroll
        for (int i = 0; i < TM; i++)
            rmax[i] = fmaxf(rmax[i], __shfl_xor_sync(0xffffffffu, rmax[i], o));
    }
    if (tx == 0) {
        float* out = g_maxdot + (size_t)pair * PP + row0 + ty * TM;
#pragma unroll
        for (int i = 0; i < TM; i++) out[i] = rmax[i];
    }
}

// ---------------------------------------------------------------------------
// Kernel 3: sp = sqrt(max(2-2*smax,1e-12))/2 * mask[n1,p]; per-pair max over p
// ---------------------------------------------------------------------------
__global__ __launch_bounds__(256) void sp_kernel(const float* __restrict__ mask) {
    const int pair = blockIdx.x;  // 128
    const int n1 = (pair >> 3) & 7;
    const int tid = threadIdx.x;
    __shared__ float red[256];
    float m = -1.0f;
    for (int p = tid; p < PP; p += 256) {
        float s  = g_maxdot[pair * PP + p];
        float d2 = fmaxf(2.0f - 2.0f * s, 1e-12f);
        float sp = sqrtf(d2) * 0.5f * mask[n1 * PP + p];
        g_sp[pair * PP + p] = sp;
        m = fmaxf(m, sp);
    }
    red[tid] = m;
    __syncthreads();
    for (int s = 128; s > 0; s >>= 1) {
        if (tid < s) red[tid] = fmaxf(red[tid], red[tid + s]);
        __syncthreads();
    }
    if (tid == 0) g_maxp[pair] = red[0];
}

// ---------------------------------------------------------------------------
// Kernel 4: spbar[n1,p] = mean over (l,n2) of sp
// ---------------------------------------------------------------------------
__global__ __launch_bounds__(256) void spbar_kernel() {
    int idx = blockIdx.x * 256 + threadIdx.x;  // 8192
    if (idx >= NN1 * PP) return;
    int n1 = idx >> 10;
    int p  = idx & (PP - 1);
    float s = 0.f;
#pragma unroll
    for (int l = 0; l < LL; l++)
#pragma unroll
        for (int n2 = 0; n2 < NN2; n2++)
            s += g_sp[(((size_t)l * NN1 + n1) * NN2 + n2) * PP + p];
    g_spbar[idx] = s * (1.0f / (LL * NN2));
}

// ---------------------------------------------------------------------------
// Kernel 5: scores[n1] = mean over (l,n2) of maxp  -> out[0..7]
// ---------------------------------------------------------------------------
__global__ void scores_kernel(float* __restrict__ out) {
    int n1 = threadIdx.x;
    if (n1 < NN1) {
        float s = 0.f;
#pragma unroll
        for (int l = 0; l < LL; l++)
#pragma unroll
            for (int n2 = 0; n2 < NN2; n2++)
                s += g_maxp[(l * NN1 + n1) * NN2 + n2];
        out[n1] = s * (1.0f / (LL * NN2));
    }
}

// ---------------------------------------------------------------------------
// Kernel 6: bilinear resize 32x32 -> 512x512 (half-pixel centers, edge clamp)
// out layout: scores at [0..7], pixels at [8 ..)
// ---------------------------------------------------------------------------
__global__ __launch_bounds__(256) void resize_kernel(float* __restrict__ out) {
    int idx = blockIdx.x * 256 + threadIdx.x;
    if (idx >= NN1 * IMG * IMG) return;
    int n1  = idx >> 18;
    int rem = idx & (IMG * IMG - 1);
    int y = rem >> 9;
    int x = rem & (IMG - 1);

    float sy = (y + 0.5f) * (1.0f / 16.0f) - 0.5f;
    float sx = (x + 0.5f) * (1.0f / 16.0f) - 0.5f;
    int y0 = (int)floorf(sy);
    int x0 = (int)floorf(sx);
    float wy = sy - (float)y0;
    float wx = sx - (float)x0;
    int y0c = min(max(y0, 0), PH - 1);
    int y1c = min(max(y0 + 1, 0), PH - 1);
    int x0c = min(max(x0, 0), PW - 1);
    int x1c = min(max(x0 + 1, 0), PW - 1);

    const float* sb = g_spbar + n1 * PP;
    float v00 = sb[y0c * PW + x0c];
    float v01 = sb[y0c * PW + x1c];
    float v10 = sb[y1c * PW + x0c];
    float v11 = sb[y1c * PW + x1c];
    float v = (1.f - wy) * ((1.f - wx) * v00 + wx * v01)
            +        wy  * ((1.f - wx) * v10 + wx * v11);
    out[8 + idx] = v;
}

// ---------------------------------------------------------------------------
extern "C" void kernel_launch(void* const* d_in, const int* in_sizes, int n_in,
                              void* d_out, int out_size) {
    const float* feats  = (const float*)d_in[0];
    const float* nfeats = (const float*)d_in[1];
    const float* mask   = (const float*)d_in[2];
    float* out = (float*)d_out;

    const int rows = LL * NN1 * PP;  // 16384 rows per tensor

    normalize_kernel<<<rows / 8, 256>>>(feats, 0, rows);
    normalize_kernel<<<rows / 8, 256>>>(nfeats, 1, rows);

    dim3 grid(PP / BM, LL * NN1 * NN2);  // (8, 128)
    distmax_kernel<<<grid, 256>>>();

    sp_kernel<<<LL * NN1 * NN2, 256>>>(mask);
    spbar_kernel<<<(NN1 * PP + 255) / 256, 256>>>();
    scores_kernel<<<1, 32>>>(out);
    resize_kernel<<<(NN1 * IMG * IMG + 255) / 256, 256>>>(out);
}

// round 2
// speedup vs baseline: 3.1947x; 3.1947x over previous
#include <cuda_runtime.h>
#include <math.h>
#include <stdint.h>

#define LL 2
#define NN1 8
#define NN2 8
#define PP 1024
#define DD 768
#define PH 32
#define PW 32
#define IMG 512

// Scratch (device globals; no allocation allowed)
__device__ float g_fa[LL * NN1 * PP * DD];      // normalized feats (tf32-rounded)
__device__ float g_fb[LL * NN2 * PP * DD];      // normalized nfeats (tf32-rounded)
__device__ float g_maxdot[LL * NN1 * NN2 * PP]; // max_p2 cos-sim
__device__ float g_sp[LL * NN1 * NN2 * PP];     // sp values
__device__ float g_maxp[LL * NN1 * NN2];        // max_p sp per (l,n1,n2)
__device__ float g_spbar[NN1 * PP];             // mean over (l,n2) of sp

__device__ __forceinline__ float tf32r(float x) {
    uint32_t o;
    asm("cvt.rna.tf32.f32 %0, %1;" : "=r"(o) : "f"(x));
    return __uint_as_float(o);
}

// ---------------------------------------------------------------------------
// Kernel 1: L2-normalize rows of [rows, 768], round to tf32. One warp per row.
// ---------------------------------------------------------------------------
__global__ __launch_bounds__(256) void normalize_kernel(const float* __restrict__ in,
                                                        int which, int nrows) {
    int row  = blockIdx.x * 8 + (threadIdx.x >> 5);
    int lane = threadIdx.x & 31;
    if (row >= nrows) return;
    float* outbase = which ? g_fb : g_fa;
    const float4* src = (const float4*)(in + (size_t)row * DD);
    float4* dst = (float4*)(outbase + (size_t)row * DD);

    float4 v[6];
    float ss = 0.f;
#pragma unroll
    for (int i = 0; i < 6; i++) {
        v[i] = src[lane + 32 * i];
        ss += v[i].x * v[i].x + v[i].y * v[i].y + v[i].z * v[i].z + v[i].w * v[i].w;
    }
#pragma unroll
    for (int o = 16; o > 0; o >>= 1) ss += __shfl_xor_sync(0xffffffffu, ss, o);
    float inv = 1.0f / sqrtf(ss);
#pragma unroll
    for (int i = 0; i < 6; i++) {
        v[i].x = tf32r(v[i].x * inv); v[i].y = tf32r(v[i].y * inv);
        v[i].z = tf32r(v[i].z * inv); v[i].w = tf32r(v[i].w * inv);
        dst[lane + 32 * i] = v[i];
    }
}

// ---------------------------------------------------------------------------
// Kernel 2: fused TF32 tensor-core GEMM + row-max.
// Pair = (l,n1,n2): S = A[1024,768]*B[1024,768]^T; keep row max over all cols.
// Block: 128-row strip of A, loops over 8 column tiles of 128.
// 256 threads = 8 warps (2m x 4n), warp tile 64x32, mma.m16n8k8.tf32.
// BK=16, cp.async double-buffered, smem stride 20 words (conflict-free frags).
// ---------------------------------------------------------------------------
#define BM 128
#define BN 128
#define BK 16
#define STRIDE 20              // words per smem row (16 + 4 pad)
#define BUF_WORDS (2 * 128 * STRIDE)   // As + Bs per buffer = 5120 words
#define BS_OFF (128 * STRIDE)          // Bs offset within buffer = 2560 words

#define CP16(dst_u32, src_ptr) \
    asm volatile("cp.async.cg.shared.global [%0], [%1], 16;\n" :: "r"(dst_u32), "l"(src_ptr))

__global__ __launch_bounds__(256) void distmax_tc() {
    __shared__ float smem[2 * BUF_WORDS + 4 * 128];
    float* part = smem + 2 * BUF_WORDS;

    const int pair = blockIdx.y;          // ((l*8 + n1)*8 + n2)
    const int l  = pair >> 6;
    const int n1 = (pair >> 3) & 7;
    const int n2 = pair & 7;
    const float* __restrict__ A = g_fa + (((size_t)l * NN1 + n1) * PP) * DD;
    const float* __restrict__ B = g_fb + (((size_t)l * NN2 + n2) * PP) * DD;
    const int row0 = blockIdx.x * BM;

    const int tid  = threadIdx.x;
    const int lane = tid & 31;
    const int warp = tid >> 5;
    const int wm = warp >> 2;        // 0..1
    const int wn = warp & 3;         // 0..3
    const int g  = lane >> 2;        // 0..7
    const int t  = lane & 3;         // 0..3

    // gmem load mapping: thread loads float4 at (row lr, col lc) and (lr+64, lc)
    const int lr = tid >> 2;
    const int lc = (tid & 3) * 4;

    const float* Abase0 = A + (size_t)(row0 + lr) * DD + lc;
    const float* Abase1 = Abase0 + (size_t)64 * DD;

    uint32_t smem_u32 = (uint32_t)__cvta_generic_to_shared(smem);
    const uint32_t dA0 = (lr * STRIDE + lc) * 4;
    const uint32_t dA1 = ((lr + 64) * STRIDE + lc) * 4;
    const uint32_t dB0 = (BS_OFF + lr * STRIDE + lc) * 4;
    const uint32_t dB1 = (BS_OFF + (lr + 64) * STRIDE + lc) * 4;

    // fragment smem bases (word offsets)
    const int a_base = (wm * 64 + g) * STRIDE + t;
    const int b_base = (wn * 32 + g) * STRIDE + t;

    float rmax[4][2];
#pragma unroll
    for (int i = 0; i < 4; i++) { rmax[i][0] = -2.f; rmax[i][1] = -2.f; }

    for (int ct = 0; ct < PP / BN; ct++) {
        const float* Bbase0 = B + (size_t)(ct * BN + lr) * DD + lc;
        const float* Bbase1 = Bbase0 + (size_t)64 * DD;

        float acc[4][4][4];
#pragma unroll
        for (int mi = 0; mi < 4; mi++)
#pragma unroll
            for (int ni = 0; ni < 4; ni++)
#pragma unroll
                for (int r = 0; r < 4; r++) acc[mi][ni][r] = 0.f;

        // prime pipeline: stage 0 -> buffer 0
        {
            uint32_t s = smem_u32;
            CP16(s + dA0, Abase0);
            CP16(s + dA1, Abase1);
            CP16(s + dB0, Bbase0);
            CP16(s + dB1, Bbase1);
            asm volatile("cp.async.commit_group;\n");
        }

        for (int ks = 0; ks < DD / BK; ks++) {
            const int cur = ks & 1;
            if (ks < DD / BK - 1) {
                const int k0 = (ks + 1) * BK;
                uint32_t s = smem_u32 + (cur ^ 1) * (BUF_WORDS * 4);
                CP16(s + dA0, Abase0 + k0);
                CP16(s + dA1, Abase1 + k0);
                CP16(s + dB0, Bbase0 + k0);
                CP16(s + dB1, Bbase1 + k0);
                asm volatile("cp.async.commit_group;\n");
                asm volatile("cp.async.wait_group 1;\n");
            } else {
                asm volatile("cp.async.wait_group 0;\n");
            }
            __syncthreads();

            const float* As = smem + cur * BUF_WORDS;
            const float* Bs = As + BS_OFF;

#pragma unroll
            for (int k8 = 0; k8 < 2; k8++) {
                uint32_t a[4][4], b[4][2];
#pragma unroll
                for (int mi = 0; mi < 4; mi++) {
                    const float* p = As + a_base + mi * (16 * STRIDE) + k8 * 8;
                    a[mi][0] = __float_as_uint(p[0]);
                    a[mi][1] = __float_as_uint(p[8 * STRIDE]);
                    a[mi][2] = __float_as_uint(p[4]);
                    a[mi][3] = __float_as_uint(p[8 * STRIDE + 4]);
                }
#pragma unroll
                for (int ni = 0; ni < 4; ni++) {
                    const float* p = Bs + b_base + ni * (8 * STRIDE) + k8 * 8;
                    b[ni][0] = __float_as_uint(p[0]);
                    b[ni][1] = __float_as_uint(p[4]);
                }
#pragma unroll
                for (int mi = 0; mi < 4; mi++)
#pragma unroll
                    for (int ni = 0; ni < 4; ni++) {
                        asm volatile(
                            "mma.sync.aligned.m16n8k8.row.col.f32.tf32.tf32.f32 "
                            "{%0,%1,%2,%3},{%4,%5,%6,%7},{%8,%9},{%0,%1,%2,%3};\n"
                            : "+f"(acc[mi][ni][0]), "+f"(acc[mi][ni][1]),
                              "+f"(acc[mi][ni][2]), "+f"(acc[mi][ni][3])
                            : "r"(a[mi][0]), "r"(a[mi][1]), "r"(a[mi][2]), "r"(a[mi][3]),
                              "r"(b[ni][0]), "r"(b[ni][1]));
                    }
            }
            __syncthreads();
        }

        // fold this column tile into running row max
        // c0,c1 -> row g; c2,c3 -> row g+8
#pragma unroll
        for (int mi = 0; mi < 4; mi++) {
            float m0 = -2.f, m1 = -2.f;
#pragma unroll
            for (int ni = 0; ni < 4; ni++) {
                m0 = fmaxf(m0, fmaxf(acc[mi][ni][0], acc[mi][ni][1]));
                m1 = fmaxf(m1, fmaxf(acc[mi][ni][2], acc[mi][ni][3]));
            }
            rmax[mi][0] = fmaxf(rmax[mi][0], m0);
            rmax[mi][1] = fmaxf(rmax[mi][1], m1);
        }
    }

    // reduce across the 4 lanes sharing g (t = lane&3)
#pragma unroll
    for (int o = 1; o <= 2; o <<= 1) {
#pragma unroll
        for (int mi = 0; mi < 4; mi++) {
            rmax[mi][0] = fmaxf(rmax[mi][0], __shfl_xor_sync(0xffffffffu, rmax[mi][0], o));
            rmax[mi][1] = fmaxf(rmax[mi][1], __shfl_xor_sync(0xffffffffu, rmax[mi][1], o));
        }
    }
    if (t == 0) {
#pragma unroll
        for (int mi = 0; mi < 4; mi++) {
            int r = wm * 64 + mi * 16 + g;
            part[wn * 128 + r] = rmax[mi][0];
            part[wn * 128 + r + 8] = rmax[mi][1];
        }
    }
    __syncthreads();
    if (tid < 128) {
        float v = fmaxf(fmaxf(part[tid], part[128 + tid]),
                        fmaxf(part[256 + tid], part[384 + tid]));
        g_maxdot[(size_t)pair * PP + row0 + tid] = v;
    }
}

// ---------------------------------------------------------------------------
// Kernel 3: sp = sqrt(max(2-2*smax,1e-12))/2 * mask[n1,p]; per-pair max over p
// ---------------------------------------------------------------------------
__global__ __launch_bounds__(256) void sp_kernel(const float* __restrict__ mask) {
    const int pair = blockIdx.x;
    const int n1 = (pair >> 3) & 7;
    const int tid = threadIdx.x;
    __shared__ float red[256];
    float m = -1.0f;
    for (int p = tid; p < PP; p += 256) {
        float s  = g_maxdot[pair * PP + p];
        float d2 = fmaxf(2.0f - 2.0f * s, 1e-12f);
        float sp = sqrtf(d2) * 0.5f * mask[n1 * PP + p];
        g_sp[pair * PP + p] = sp;
        m = fmaxf(m, sp);
    }
    red[tid] = m;
    __syncthreads();
    for (int s = 128; s > 0; s >>= 1) {
        if (tid < s) red[tid] = fmaxf(red[tid], red[tid + s]);
        __syncthreads();
    }
    if (tid == 0) g_maxp[pair] = red[0];
}

// ---------------------------------------------------------------------------
// Kernel 4: spbar[n1,p] = mean over (l,n2) of sp
// ---------------------------------------------------------------------------
__global__ __launch_bounds__(256) void spbar_kernel() {
    int idx = blockIdx.x * 256 + threadIdx.x;
    if (idx >= NN1 * PP) return;
    int n1 = idx >> 10;
    int p  = idx & (PP - 1);
    float s = 0.f;
#pragma unroll
    for (int l = 0; l < LL; l++)
#pragma unroll
        for (int n2 = 0; n2 < NN2; n2++)
            s += g_sp[(((size_t)l * NN1 + n1) * NN2 + n2) * PP + p];
    g_spbar[idx] = s * (1.0f / (LL * NN2));
}

// ---------------------------------------------------------------------------
// Kernel 5: scores[n1] = mean over (l,n2) of maxp -> out[0..7]
// ---------------------------------------------------------------------------
__global__ void scores_kernel(float* __restrict__ out) {
    int n1 = threadIdx.x;
    if (n1 < NN1) {
        float s = 0.f;
#pragma unroll
        for (int l = 0; l < LL; l++)
#pragma unroll
            for (int n2 = 0; n2 < NN2; n2++)
                s += g_maxp[(l * NN1 + n1) * NN2 + n2];
        out[n1] = s * (1.0f / (LL * NN2));
    }
}

// ---------------------------------------------------------------------------
// Kernel 6: bilinear resize 32x32 -> 512x512 (half-pixel centers, edge clamp)
// ---------------------------------------------------------------------------
__global__ __launch_bounds__(256) void resize_kernel(float* __restrict__ out) {
    int idx = blockIdx.x * 256 + threadIdx.x;
    if (idx >= NN1 * IMG * IMG) return;
    int n1  = idx >> 18;
    int rem = idx & (IMG * IMG - 1);
    int y = rem >> 9;
    int x = rem & (IMG - 1);

    float sy = (y + 0.5f) * (1.0f / 16.0f) - 0.5f;
    float sx = (x + 0.5f) * (1.0f / 16.0f) - 0.5f;
    int y0 = (int)floorf(sy);
    int x0 = (int)floorf(sx);
    float wy = sy - (float)y0;
    float wx = sx - (float)x0;
    int y0c = min(max(y0, 0), PH - 1);
    int y1c = min(max(y0 + 1, 0), PH - 1);
    int x0c = min(max(x0, 0), PW - 1);
    int x1c = min(max(x0 + 1, 0), PW - 1);

    const float* sb = g_spbar + n1 * PP;
    float v00 = sb[y0c * PW + x0c];
    float v01 = sb[y0c * PW + x1c];
    float v10 = sb[y1c * PW + x0c];
    float v11 = sb[y1c * PW + x1c];
    float v = (1.f - wy) * ((1.f - wx) * v00 + wx * v01)
            +        wy  * ((1.f - wx) * v10 + wx * v11);
    out[8 + idx] = v;
}

// ---------------------------------------------------------------------------
extern "C" void kernel_launch(void* const* d_in, const int* in_sizes, int n_in,
                              void* d_out, int out_size) {
    const float* feats  = (const float*)d_in[0];
    const float* nfeats = (const float*)d_in[1];
    const float* mask   = (const float*)d_in[2];
    float* out = (float*)d_out;

    const int rows = LL * NN1 * PP;  // 16384 rows per tensor

    normalize_kernel<<<rows / 8, 256>>>(feats, 0, rows);
    normalize_kernel<<<rows / 8, 256>>>(nfeats, 1, rows);

    dim3 grid(PP / BM, LL * NN1 * NN2);  // (8, 128)
    distmax_tc<<<grid, 256>>>();

    sp_kernel<<<LL * NN1 * NN2, 256>>>(mask);
    spbar_kernel<<<(NN1 * PP + 255) / 256, 256>>>();
    scores_kernel<<<1, 32>>>(out);
    resize_kernel<<<(NN1 * IMG * IMG + 255) / 256, 256>>>(out);
}

// round 4
// speedup vs baseline: 5.3739x; 1.6821x over previous
#include <cuda_runtime.h>
#include <cuda_bf16.h>
#include <math.h>
#include <stdint.h>

#define LL 2
#define NN1 8
#define NN2 8
#define PP 1024
#define DD 768
#define PH 32
#define PW 32
#define IMG 512

// Scratch (device globals; no allocation allowed)
__device__ __nv_bfloat16 g_fa[LL * NN1 * PP * DD];  // normalized feats (bf16)
__device__ __nv_bfloat16 g_fb[LL * NN2 * PP * DD];  // normalized nfeats (bf16)
__device__ float g_maxdot[LL * NN1 * NN2 * PP];     // max_p2 cos-sim
__device__ float g_sp[LL * NN1 * NN2 * PP];
__device__ float g_maxp[LL * NN1 * NN2];
__device__ float g_spbar[NN1 * PP];

// ---------------------------------------------------------------------------
// Kernel 1: L2-normalize rows of [rows, 768] -> bf16. One warp per row.
// ---------------------------------------------------------------------------
__global__ __launch_bounds__(256) void normalize_kernel(const float* __restrict__ in,
                                                        int which, int nrows) {
    int row  = blockIdx.x * 8 + (threadIdx.x >> 5);
    int lane = threadIdx.x & 31;
    if (row >= nrows) return;
    __nv_bfloat16* outbase = which ? g_fb : g_fa;
    const float4* src = (const float4*)(in + (size_t)row * DD);
    __nv_bfloat162* dst = (__nv_bfloat162*)(outbase + (size_t)row * DD);

    float4 v[6];
    float ss = 0.f;
#pragma unroll
    for (int i = 0; i < 6; i++) {
        v[i] = src[lane + 32 * i];
        ss += v[i].x * v[i].x + v[i].y * v[i].y + v[i].z * v[i].z + v[i].w * v[i].w;
    }
#pragma unroll
    for (int o = 16; o > 0; o >>= 1) ss += __shfl_xor_sync(0xffffffffu, ss, o);
    float inv = 1.0f / sqrtf(ss);
#pragma unroll
    for (int i = 0; i < 6; i++) {
        int e = lane + 32 * i;
        dst[e * 2 + 0] = __floats2bfloat162_rn(v[i].x * inv, v[i].y * inv);
        dst[e * 2 + 1] = __floats2bfloat162_rn(v[i].z * inv, v[i].w * inv);
    }
}

// ---------------------------------------------------------------------------
// Kernel 2: fused bf16 mma.sync GEMM + row-max.
// Pair = (l,n1,n2): S = A[1024,768]*B[1024,768]^T; keep row max over columns.
// Block: 128-row strip of A; loops over 8 column tiles of 128.
// 256 threads = 8 warps (2m x 4n), warp tile 64x32, mma.m16n8k16.bf16.
// BK=32 halves, cp.async double-buffered, smem rows padded to 40 halves.
// ---------------------------------------------------------------------------
#define BM 128
#define BN 128
#define BK 32
#define RS 40     // smem row stride in halves (32 + 8 pad) -> 80 bytes

#define CP16(dst_u32, src_ptr) \
    asm volatile("cp.async.cg.shared.global [%0], [%1], 16;\n" :: "r"(dst_u32), "l"(src_ptr))

__device__ __forceinline__ void ldsm4(uint32_t* r, uint32_t addr) {
    asm volatile("ldmatrix.sync.aligned.m8n8.x4.shared.b16 {%0,%1,%2,%3}, [%4];"
                 : "=r"(r[0]), "=r"(r[1]), "=r"(r[2]), "=r"(r[3]) : "r"(addr));
}

__global__ __launch_bounds__(256, 1) void distmax_bf16() {
    __shared__ __align__(16) __nv_bfloat16 sA[2][BM * RS];
    __shared__ __align__(16) __nv_bfloat16 sB[2][BN * RS];
    __shared__ float part[4 * 128];

    const int pair = blockIdx.y;          // ((l*8 + n1)*8 + n2)
    const int l  = pair >> 6;
    const int n1 = (pair >> 3) & 7;
    const int n2 = pair & 7;
    const __nv_bfloat16* __restrict__ A =
        g_fa + (((size_t)(l * NN1 + n1)) * PP + blockIdx.x * BM) * DD;
    const __nv_bfloat16* __restrict__ B = g_fb + ((size_t)(l * NN2 + n2)) * PP * DD;

    const int tid  = threadIdx.x;
    const int lane = tid & 31;
    const int warp = tid >> 5;
    const int wm = warp >> 2;        // 0..1
    const int wn = warp & 3;         // 0..3
    const int g  = lane >> 2;        // 0..7
    const int t4 = lane & 3;         // 0..3
    const int sub = lane >> 3;       // 0..3 (ldmatrix sub-matrix)
    const int lr8 = lane & 7;

    // cp.async mapping: idx -> (row = idx>>2, 16B chunk c = idx&3)
    const int ldr = tid >> 2;        // 0..63 (+64 for second half)
    const int ldc = tid & 3;

    uint32_t sA0 = (uint32_t)__cvta_generic_to_shared(&sA[0][0]);
    uint32_t sB0 = (uint32_t)__cvta_generic_to_shared(&sB[0][0]);
    const uint32_t dOff0 = (uint32_t)(ldr * RS * 2 + ldc * 16);
    const uint32_t dOff1 = (uint32_t)((ldr + 64) * RS * 2 + ldc * 16);

    const __nv_bfloat16* aSrc0 = A + (size_t)ldr * DD + ldc * 8;
    const __nv_bfloat16* aSrc1 = aSrc0 + (size_t)64 * DD;

    // ldmatrix per-lane byte offsets (within current buffer)
    // A: matrix sub -> rows base + (sub&1)*8 + lr8, k offset (sub>>1)*8
    const uint32_t aLds = (uint32_t)(((wm * 64 + (sub & 1) * 8 + lr8) * RS +
                                      (sub >> 1) * 8) * 2);
    // B: matrix sub -> cols base + (sub>>1)*8 + lr8, k offset (sub&1)*8
    const uint32_t bLds = (uint32_t)(((wn * 32 + (sub >> 1) * 8 + lr8) * RS +
                                      (sub & 1) * 8) * 2);

    float rmax[4][2];
#pragma unroll
    for (int i = 0; i < 4; i++) { rmax[i][0] = -2.f; rmax[i][1] = -2.f; }

    for (int ct = 0; ct < PP / BN; ct++) {
        const __nv_bfloat16* bSrc0 = B + (size_t)(ct * BN + ldr) * DD + ldc * 8;
        const __nv_bfloat16* bSrc1 = bSrc0 + (size_t)64 * DD;

        float acc[4][4][4];
#pragma unroll
        for (int mi = 0; mi < 4; mi++)
#pragma unroll
            for (int ni = 0; ni < 4; ni++)
#pragma unroll
                for (int r = 0; r < 4; r++) acc[mi][ni][r] = 0.f;

        // prime: stage 0 -> buffer 0
        CP16(sA0 + dOff0, aSrc0);
        CP16(sA0 + dOff1, aSrc1);
        CP16(sB0 + dOff0, bSrc0);
        CP16(sB0 + dOff1, bSrc1);
        asm volatile("cp.async.commit_group;\n");

        for (int ks = 0; ks < DD / BK; ks++) {
            const int cur = ks & 1;
            if (ks < DD / BK - 1) {
                const int k0 = (ks + 1) * BK;
                uint32_t bufo = (uint32_t)((cur ^ 1) * BM * RS * 2);
                CP16(sA0 + bufo + dOff0, aSrc0 + k0);
                CP16(sA0 + bufo + dOff1, aSrc1 + k0);
                CP16(sB0 + bufo + dOff0, bSrc0 + k0);
                CP16(sB0 + bufo + dOff1, bSrc1 + k0);
                asm volatile("cp.async.commit_group;\n");
                asm volatile("cp.async.wait_group 1;\n");
            } else {
                asm volatile("cp.async.wait_group 0;\n");
            }
            __syncthreads();

            const uint32_t aBuf = sA0 + (uint32_t)(cur * BM * RS * 2);
            const uint32_t bBuf = sB0 + (uint32_t)(cur * BN * RS * 2);

#pragma unroll
            for (int k16 = 0; k16 < 2; k16++) {
                uint32_t a[4][4], b[2][4];
#pragma unroll
                for (int mi = 0; mi < 4; mi++)
                    ldsm4(a[mi], aBuf + aLds + (uint32_t)(mi * 16 * RS * 2 + k16 * 32));
#pragma unroll
                for (int np = 0; np < 2; np++)
                    ldsm4(b[np], bBuf + bLds + (uint32_t)(np * 16 * RS * 2 + k16 * 32));
#pragma unroll
                for (int mi = 0; mi < 4; mi++)
#pragma unroll
                    for (int ni = 0; ni < 4; ni++) {
                        asm volatile(
                            "mma.sync.aligned.m16n8k16.row.col.f32.bf16.bf16.f32 "
                            "{%0,%1,%2,%3},{%4,%5,%6,%7},{%8,%9},{%0,%1,%2,%3};\n"
                            : "+f"(acc[mi][ni][0]), "+f"(acc[mi][ni][1]),
                              "+f"(acc[mi][ni][2]), "+f"(acc[mi][ni][3])
                            : "r"(a[mi][0]), "r"(a[mi][1]), "r"(a[mi][2]), "r"(a[mi][3]),
                              "r"(b[ni >> 1][(ni & 1) * 2]), "r"(b[ni >> 1][(ni & 1) * 2 + 1]));
                    }
            }
            __syncthreads();
        }

        // fold this column tile into running row max
        // c0,c1 -> row g; c2,c3 -> row g+8
#pragma unroll
        for (int mi = 0; mi < 4; mi++) {
            float m0 = -2.f, m1 = -2.f;
#pragma unroll
            for (int ni = 0; ni < 4; ni++) {
                m0 = fmaxf(m0, fmaxf(acc[mi][ni][0], acc[mi][ni][1]));
                m1 = fmaxf(m1, fmaxf(acc[mi][ni][2], acc[mi][ni][3]));
            }
            rmax[mi][0] = fmaxf(rmax[mi][0], m0);
            rmax[mi][1] = fmaxf(rmax[mi][1], m1);
        }
    }

    // reduce across the 4 lanes sharing g (t4 = lane&3)
#pragma unroll
    for (int o = 1; o <= 2; o <<= 1) {
#pragma unroll
        for (int mi = 0; mi < 4; mi++) {
            rmax[mi][0] = fmaxf(rmax[mi][0], __shfl_xor_sync(0xffffffffu, rmax[mi][0], o));
            rmax[mi][1] = fmaxf(rmax[mi][1], __shfl_xor_sync(0xffffffffu, rmax[mi][1], o));
        }
    }
    if (t4 == 0) {
#pragma unroll
        for (int mi = 0; mi < 4; mi++) {
            int r = wm * 64 + mi * 16 + g;
            part[wn * 128 + r] = rmax[mi][0];
            part[wn * 128 + r + 8] = rmax[mi][1];
        }
    }
    __syncthreads();
    if (tid < 128) {
        float v = fmaxf(fmaxf(part[tid], part[128 + tid]),
                        fmaxf(part[256 + tid], part[384 + tid]));
        g_maxdot[(size_t)pair * PP + blockIdx.x * BM + tid] = v;
    }
}

// ---------------------------------------------------------------------------
// Kernel 3: sp = sqrt(max(2-2*smax,1e-12))/2 * mask[n1,p]; per-pair max over p
// ---------------------------------------------------------------------------
__global__ __launch_bounds__(256) void sp_kernel(const float* __restrict__ mask) {
    const int pair = blockIdx.x;
    const int n1 = (pair >> 3) & 7;
    const int tid = threadIdx.x;
    __shared__ float red[256];
    float m = -1.0f;
    for (int p = tid; p < PP; p += 256) {
        float s  = g_maxdot[pair * PP + p];
        float d2 = fmaxf(2.0f - 2.0f * s, 1e-12f);
        float sp = sqrtf(d2) * 0.5f * mask[n1 * PP + p];
        g_sp[pair * PP + p] = sp;
        m = fmaxf(m, sp);
    }
    red[tid] = m;
    __syncthreads();
    for (int s = 128; s > 0; s >>= 1) {
        if (tid < s) red[tid] = fmaxf(red[tid], red[tid + s]);
        __syncthreads();
    }
    if (tid == 0) g_maxp[pair] = red[0];
}

// ---------------------------------------------------------------------------
// Kernel 4: spbar[n1,p] = mean over (l,n2) of sp
// ---------------------------------------------------------------------------
__global__ __launch_bounds__(256) void spbar_kernel() {
    int idx = blockIdx.x * 256 + threadIdx.x;
    if (idx >= NN1 * PP) return;
    int n1 = idx >> 10;
    int p  = idx & (PP - 1);
    float s = 0.f;
#pragma unroll
    for (int l = 0; l < LL; l++)
#pragma unroll
        for (int n2 = 0; n2 < NN2; n2++)
            s += g_sp[(((size_t)l * NN1 + n1) * NN2 + n2) * PP + p];
    g_spbar[idx] = s * (1.0f / (LL * NN2));
}

// ---------------------------------------------------------------------------
// Kernel 5: scores[n1] = mean over (l,n2) of maxp -> out[0..7]
// ---------------------------------------------------------------------------
__global__ void scores_kernel(float* __restrict__ out) {
    int n1 = threadIdx.x;
    if (n1 < NN1) {
        float s = 0.f;
#pragma unroll
        for (int l = 0; l < LL; l++)
#pragma unroll
            for (int n2 = 0; n2 < NN2; n2++)
                s += g_maxp[(l * NN1 + n1) * NN2 + n2];
        out[n1] = s * (1.0f / (LL * NN2));
    }
}

// ---------------------------------------------------------------------------
// Kernel 6: bilinear resize 32x32 -> 512x512 (half-pixel centers, edge clamp)
// ---------------------------------------------------------------------------
__global__ __launch_bounds__(256) void resize_kernel(float* __restrict__ out) {
    int idx = blockIdx.x * 256 + threadIdx.x;
    if (idx >= NN1 * IMG * IMG) return;
    int n1  = idx >> 18;
    int rem = idx & (IMG * IMG - 1);
    int y = rem >> 9;
    int x = rem & (IMG - 1);

    float sy = (y + 0.5f) * (1.0f / 16.0f) - 0.5f;
    float sx = (x + 0.5f) * (1.0f / 16.0f) - 0.5f;
    int y0 = (int)floorf(sy);
    int x0 = (int)floorf(sx);
    float wy = sy - (float)y0;
    float wx = sx - (float)x0;
    int y0c = min(max(y0, 0), PH - 1);
    int y1c = min(max(y0 + 1, 0), PH - 1);
    int x0c = min(max(x0, 0), PW - 1);
    int x1c = min(max(x0 + 1, 0), PW - 1);

    const float* sb = g_spbar + n1 * PP;
    float v00 = sb[y0c * PW + x0c];
    float v01 = sb[y0c * PW + x1c];
    float v10 = sb[y1c * PW + x0c];
    float v11 = sb[y1c * PW + x1c];
    float v = (1.f - wy) * ((1.f - wx) * v00 + wx * v01)
            +        wy  * ((1.f - wx) * v10 + wx * v11);
    out[8 + idx] = v;
}

// ---------------------------------------------------------------------------
extern "C" void kernel_launch(void* const* d_in, const int* in_sizes, int n_in,
                              void* d_out, int out_size) {
    const float* feats  = (const float*)d_in[0];
    const float* nfeats = (const float*)d_in[1];
    const float* mask   = (const float*)d_in[2];
    float* out = (float*)d_out;

    const int rows = LL * NN1 * PP;  // 16384 rows per tensor

    normalize_kernel<<<rows / 8, 256>>>(feats, 0, rows);
    normalize_kernel<<<rows / 8, 256>>>(nfeats, 1, rows);

    dim3 grid(PP / BM, LL * NN1 * NN2);  // (8, 128)
    distmax_bf16<<<grid, 256>>>();

    sp_kernel<<<LL * NN1 * NN2, 256>>>(mask);
    spbar_kernel<<<(NN1 * PP + 255) / 256, 256>>>();
    scores_kernel<<<1, 32>>>(out);
    resize_kernel<<<(NN1 * IMG * IMG + 255) / 256, 256>>>(out);
}